// round 1
// baseline (speedup 1.0000x reference)
#include <cuda_runtime.h>
#include <math.h>
#include <stdint.h>

// Problem constants (fixed shapes)
#define B_  16
#define T_  1000
#define TT_ 2000
#define F_  512
#define H_  512
#define HH_ 1024

// ---------------- device scratch (allowed: __device__ globals) ----------------
__device__ float g_wzh [B_ * TT_ * HH_];   // BN'd pre-activations: [b][t'][0:512]=wz, [512:1024]=wh  (128MB)
__device__ float g_hseq[B_ * TT_ * H_ ];   // all hidden states over the 2000-step scan (64MB)
__device__ float g_ln  [B_ * T_  * HH_];   // layernorm output (64MB)
__device__ float g_scale[HH_];
__device__ float g_bias [HH_];
__device__ unsigned int g_cnt[8];          // per-group monotonic step counters

// ---------------- packed fp32x2 FMA (double-rate FFMA on sm_103a) ----------------
__device__ __forceinline__ float2 ffma2(float2 a, float2 b, float2 c) {
    float2 d;
    asm("fma.rn.f32x2 %0, %1, %2, %3;"
        : "=l"(reinterpret_cast<unsigned long long &>(d))
        : "l"(reinterpret_cast<unsigned long long &>(a)),
          "l"(reinterpret_cast<unsigned long long &>(b)),
          "l"(reinterpret_cast<unsigned long long &>(c)));
    return d;
}

// ---------------- prep: fold BN into per-column scale/bias; reset counters ----------------
__global__ void prep_kernel(const float* __restrict__ bz, const float* __restrict__ bh,
                            const float* __restrict__ zg, const float* __restrict__ zb,
                            const float* __restrict__ zm, const float* __restrict__ zv,
                            const float* __restrict__ hg, const float* __restrict__ hb,
                            const float* __restrict__ hm, const float* __restrict__ hv) {
    int n = threadIdx.x;  // 1024 threads
    float sc, bi;
    if (n < 512) {
        sc = zg[n] * rsqrtf(zv[n] + 1e-5f);
        bi = (bz[n] - zm[n]) * sc + zb[n];
    } else {
        int j = n - 512;
        sc = hg[j] * rsqrtf(hv[j] + 1e-5f);
        bi = (bh[j] - hm[j]) * sc + hb[j];
    }
    g_scale[n] = sc;
    g_bias[n]  = bi;
    if (n < 8) g_cnt[n] = 0u;
}

// ---------------- phase 1: wzh = BN(x_cat @ [Wz;Wh]^T + b) ----------------
// C = A * B^T, A gathered rows of x_cat (32000 x 512), B rows = Wz / Wh (1024 x 512)
__global__ __launch_bounds__(256) void gemm_wzh(const float* __restrict__ x,
                                                const float* __restrict__ Wz,
                                                const float* __restrict__ Wh) {
    __shared__ __align__(16) float As[32][68];
    __shared__ __align__(16) float Bs[32][68];
    int tid = threadIdx.x;
    int tx = tid & 15, ty = tid >> 4;
    int m0 = blockIdx.y * 64, n0 = blockIdx.x * 64;

    float2 acc[4][2];
#pragma unroll
    for (int i = 0; i < 4; i++) { acc[i][0] = make_float2(0.f, 0.f); acc[i][1] = make_float2(0.f, 0.f); }

    for (int k0 = 0; k0 < 512; k0 += 32) {
#pragma unroll
        for (int u = 0; u < 2; u++) {
            int v  = tid * 2 + u;       // 0..511 float4 slots
            int mm = v >> 3;            // 0..63 row within tile
            int k4 = (v & 7) * 4;       // 0..28

            int m = m0 + mm;
            int b = m / TT_;
            int tp = m - b * TT_;
            const float* arow = (tp < T_) ? (x + ((size_t)(b * T_ + tp) << 9))
                                          : (x + ((size_t)((15 - b) * T_ + (tp - T_)) << 9));
            float4 av = *(const float4*)(arow + k0 + k4);
            As[k4 + 0][mm] = av.x; As[k4 + 1][mm] = av.y; As[k4 + 2][mm] = av.z; As[k4 + 3][mm] = av.w;

            int n = n0 + mm;
            const float* brow = (n < 512) ? (Wz + ((size_t)n << 9))
                                          : (Wh + ((size_t)(n - 512) << 9));
            float4 bv = *(const float4*)(brow + k0 + k4);
            Bs[k4 + 0][mm] = bv.x; Bs[k4 + 1][mm] = bv.y; Bs[k4 + 2][mm] = bv.z; Bs[k4 + 3][mm] = bv.w;
        }
        __syncthreads();
#pragma unroll
        for (int k = 0; k < 32; k++) {
            float4 a4 = *(const float4*)&As[k][ty * 4];
            float4 b4 = *(const float4*)&Bs[k][tx * 4];
            float2 b20 = make_float2(b4.x, b4.y), b21 = make_float2(b4.z, b4.w);
            float av[4] = {a4.x, a4.y, a4.z, a4.w};
#pragma unroll
            for (int i = 0; i < 4; i++) {
                float2 ad = make_float2(av[i], av[i]);
                acc[i][0] = ffma2(ad, b20, acc[i][0]);
                acc[i][1] = ffma2(ad, b21, acc[i][1]);
            }
        }
        __syncthreads();
    }
#pragma unroll
    for (int i = 0; i < 4; i++) {
        int m = m0 + ty * 4 + i;
        float* orow = g_wzh + (size_t)m * HH_ + n0 + tx * 4;
        int n = n0 + tx * 4;
        orow[0] = acc[i][0].x * g_scale[n + 0] + g_bias[n + 0];
        orow[1] = acc[i][0].y * g_scale[n + 1] + g_bias[n + 1];
        orow[2] = acc[i][1].x * g_scale[n + 2] + g_bias[n + 2];
        orow[3] = acc[i][1].y * g_scale[n + 3] + g_bias[n + 3];
    }
}

// ---------------- phase 2: persistent scan ----------------
// 128 CTAs = 8 groups x 16 CTAs. Group g owns batches {2g, 2g+1}.
// CTA i of a group owns U rows [32i,32i+32) (z-part) and [512+32i, 512+32i+32) (h-part),
// held entirely in registers (64 floats/thread at 512 threads). h broadcast via smem.
__global__ __launch_bounds__(512, 1) void scan_kernel(const float* __restrict__ U) {
    __shared__ float h_sm[2][512];
    __shared__ float red[2][8][64];

    int t   = threadIdx.x;
    int grp = blockIdx.x >> 4;   // 0..7
    int ci  = blockIdx.x & 15;   // 0..15 CTA within group
    int b0  = grp * 2;

    int r = t & 63;              // local row 0..63  (0..31 = z-rows, 32..63 = h-rows)
    int c = t >> 6;              // k-chunk 0..7 (64 k each)
    int urow = (r < 32) ? (ci * 32 + r) : (512 + ci * 32 + (r - 32));

    // load this thread's U slice into registers (one-time)
    const float2* Up = (const float2*)(U + (size_t)urow * 512 + c * 64);
    float2 Ureg[32];
#pragma unroll
    for (int q = 0; q < 32; q++) Ureg[q] = __ldg(&Up[q]);

    // zero initial hidden state
    for (int idx = t; idx < 1024; idx += 512) ((float*)h_sm)[idx] = 0.f;

    // gate-thread setup + prefetch step-0 wz/wh
    int bb = t >> 5, j = t & 31;           // only meaningful for t<64
    int bcur = b0 + bb;
    int cz = ci * 32 + j, ch = 512 + ci * 32 + j;
    float nz = 0.f, nh = 0.f;
    if (t < 64) {
        nz = __ldg(&g_wzh[(size_t)bcur * TT_ * HH_ + cz]);
        nh = __ldg(&g_wzh[(size_t)bcur * TT_ * HH_ + ch]);
    }
    __syncthreads();

    for (int s = 0; s < TT_; s++) {
        // matvec: partial dot over this thread's 64-k chunk, both batches
        float2 a0 = make_float2(0.f, 0.f), a1 = make_float2(0.f, 0.f);
        const float2* h0 = (const float2*)&h_sm[0][c * 64];
        const float2* h1 = (const float2*)&h_sm[1][c * 64];
#pragma unroll
        for (int q = 0; q < 32; q++) {
            a0 = ffma2(Ureg[q], h0[q], a0);
            a1 = ffma2(Ureg[q], h1[q], a1);
        }
        red[0][c][r] = a0.x + a0.y;
        red[1][c][r] = a1.x + a1.y;
        __syncthreads();

        if (t < 64) {
            float uz = 0.f, uh = 0.f;
#pragma unroll
            for (int cc = 0; cc < 8; cc++) { uz += red[bb][cc][j]; uh += red[bb][cc][32 + j]; }
            float zt = __fdividef(1.f, 1.f + __expf(-(nz + uz)));
            float hc = fmaxf(nh + uh, 0.f);
            float hp = h_sm[bb][ci * 32 + j];
            float hn = zt * hp + (1.f - zt) * hc;
            g_hseq[((size_t)bcur * TT_ + s) * H_ + ci * 32 + j] = hn;
            if (s + 1 < TT_) {
                nz = __ldg(&g_wzh[((size_t)bcur * TT_ + s + 1) * HH_ + cz]);
                nh = __ldg(&g_wzh[((size_t)bcur * TT_ + s + 1) * HH_ + ch]);
            }
        }
        __threadfence();
        __syncthreads();
        if (t == 0) {
            atomicAdd(&g_cnt[grp], 1u);
            unsigned int target = (unsigned int)(16 * (s + 1));
            unsigned int v;
            do {
                asm volatile("ld.acquire.gpu.u32 %0, [%1];" : "=r"(v) : "l"(&g_cnt[grp]) : "memory");
            } while (v < target);
        }
        __syncthreads();
        // reload full h (both batches) from L2
        for (int idx = t; idx < 1024; idx += 512) {
            int b2 = idx >> 9, hh = idx & 511;
            h_sm[b2][hh] = __ldcg(&g_hseq[((size_t)(b0 + b2) * TT_ + s) * H_ + hh]);
        }
        __syncthreads();
    }
}

// ---------------- phase 3: LayerNorm over concat(h_f, h_b) ----------------
__global__ __launch_bounds__(256) void ln_kernel(const float* __restrict__ lng,
                                                 const float* __restrict__ lnb) {
    __shared__ float s_sum[8], s_sq[8];
    int row = blockIdx.x;            // 0..15999
    int b = row / T_, tt = row - b * T_;
    int tid = threadIdx.x;
    int d = tid * 4;
    const float* base = (d < 512)
        ? (g_hseq + ((size_t)b * TT_ + tt) * H_ + d)
        : (g_hseq + ((size_t)(15 - b) * TT_ + T_ + tt) * H_ + (d - 512));
    float4 v = *(const float4*)base;
    float s = v.x + v.y + v.z + v.w;
    float q = v.x * v.x + v.y * v.y + v.z * v.z + v.w * v.w;
#pragma unroll
    for (int o = 16; o > 0; o >>= 1) {
        s += __shfl_down_sync(0xffffffffu, s, o);
        q += __shfl_down_sync(0xffffffffu, q, o);
    }
    int wid = tid >> 5, lid = tid & 31;
    if (lid == 0) { s_sum[wid] = s; s_sq[wid] = q; }
    __syncthreads();
    if (tid == 0) {
        float S = 0.f, Q = 0.f;
#pragma unroll
        for (int w = 0; w < 8; w++) { S += s_sum[w]; Q += s_sq[w]; }
        s_sum[0] = S; s_sq[0] = Q;
    }
    __syncthreads();
    float mu  = s_sum[0] * (1.f / 1024.f);
    float var = s_sq[0] * (1.f / 1024.f) - mu * mu;
    float inv = rsqrtf(var + 1e-5f);
    float4 g4 = *(const float4*)(lng + d);
    float4 b4 = *(const float4*)(lnb + d);
    float4 o;
    o.x = (v.x - mu) * inv * g4.x + b4.x;
    o.y = (v.y - mu) * inv * g4.y + b4.y;
    o.z = (v.z - mu) * inv * g4.z + b4.z;
    o.w = (v.w - mu) * inv * g4.w + b4.w;
    *(float4*)(g_ln + (size_t)row * HH_ + d) = o;
}

// ---------------- phase 4: out = tanh(ln_out @ pj_W^T + pj_b) ----------------
__global__ __launch_bounds__(256) void gemm_proj(const float* __restrict__ pjW,
                                                 const float* __restrict__ pjb,
                                                 float* __restrict__ out) {
    __shared__ __align__(16) float As[32][68];
    __shared__ __align__(16) float Bs[32][68];
    int tid = threadIdx.x;
    int tx = tid & 15, ty = tid >> 4;
    int m0 = blockIdx.y * 64, n0 = blockIdx.x * 64;

    float2 acc[4][2];
#pragma unroll
    for (int i = 0; i < 4; i++) { acc[i][0] = make_float2(0.f, 0.f); acc[i][1] = make_float2(0.f, 0.f); }

    for (int k0 = 0; k0 < 1024; k0 += 32) {
#pragma unroll
        for (int u = 0; u < 2; u++) {
            int v  = tid * 2 + u;
            int mm = v >> 3;
            int k4 = (v & 7) * 4;
            float4 av = *(const float4*)(g_ln + (size_t)(m0 + mm) * HH_ + k0 + k4);
            As[k4 + 0][mm] = av.x; As[k4 + 1][mm] = av.y; As[k4 + 2][mm] = av.z; As[k4 + 3][mm] = av.w;
            float4 bv = *(const float4*)(pjW + (size_t)(n0 + mm) * HH_ + k0 + k4);
            Bs[k4 + 0][mm] = bv.x; Bs[k4 + 1][mm] = bv.y; Bs[k4 + 2][mm] = bv.z; Bs[k4 + 3][mm] = bv.w;
        }
        __syncthreads();
#pragma unroll
        for (int k = 0; k < 32; k++) {
            float4 a4 = *(const float4*)&As[k][ty * 4];
            float4 b4 = *(const float4*)&Bs[k][tx * 4];
            float2 b20 = make_float2(b4.x, b4.y), b21 = make_float2(b4.z, b4.w);
            float av[4] = {a4.x, a4.y, a4.z, a4.w};
#pragma unroll
            for (int i = 0; i < 4; i++) {
                float2 ad = make_float2(av[i], av[i]);
                acc[i][0] = ffma2(ad, b20, acc[i][0]);
                acc[i][1] = ffma2(ad, b21, acc[i][1]);
            }
        }
        __syncthreads();
    }
#pragma unroll
    for (int i = 0; i < 4; i++) {
        int m = m0 + ty * 4 + i;
        int n = n0 + tx * 4;
        float* orow = out + (size_t)m * HH_ + n;
        orow[0] = tanhf(acc[i][0].x + pjb[n + 0]);
        orow[1] = tanhf(acc[i][0].y + pjb[n + 1]);
        orow[2] = tanhf(acc[i][1].x + pjb[n + 2]);
        orow[3] = tanhf(acc[i][1].y + pjb[n + 3]);
    }
}

// ---------------- tail: x_len pass-through (if output is the flattened tuple) ----------------
__global__ void tail_kernel(const int* __restrict__ xlen, float* __restrict__ out) {
    int t = threadIdx.x;
    if (t < B_) out[(size_t)B_ * T_ * HH_ + t] = (float)xlen[t];
}

extern "C" void kernel_launch(void* const* d_in, const int* in_sizes, int n_in,
                              void* d_out, int out_size) {
    const float* x   = (const float*)d_in[0];
    const int*   xl  = (const int*)  d_in[1];
    const float* Wz  = (const float*)d_in[2];
    const float* bz  = (const float*)d_in[3];
    const float* Wh  = (const float*)d_in[4];
    const float* bh  = (const float*)d_in[5];
    const float* U   = (const float*)d_in[6];
    const float* zg  = (const float*)d_in[7];
    const float* zb  = (const float*)d_in[8];
    const float* zm  = (const float*)d_in[9];
    const float* zv  = (const float*)d_in[10];
    const float* hg  = (const float*)d_in[11];
    const float* hb  = (const float*)d_in[12];
    const float* hm  = (const float*)d_in[13];
    const float* hv  = (const float*)d_in[14];
    const float* lng = (const float*)d_in[15];
    const float* lnb = (const float*)d_in[16];
    const float* pjW = (const float*)d_in[17];
    const float* pjb = (const float*)d_in[18];
    float* out = (float*)d_out;

    prep_kernel<<<1, 1024>>>(bz, bh, zg, zb, zm, zv, hg, hb, hm, hv);
    gemm_wzh<<<dim3(16, 500), 256>>>(x, Wz, Wh);
    scan_kernel<<<128, 512>>>(U);
    ln_kernel<<<16000, 256>>>(lng, lnb);
    gemm_proj<<<dim3(16, 250), 256>>>(pjW, pjb, out);
    if (out_size >= B_ * T_ * HH_ + B_) {
        tail_kernel<<<1, 32>>>(xl, out);
    }
    (void)in_sizes; (void)n_in;
}

// round 2
// speedup vs baseline: 1.0026x; 1.0026x over previous
#include <cuda_runtime.h>
#include <math.h>
#include <stdint.h>

// Problem constants (fixed shapes)
#define B_  16
#define T_  1000
#define TT_ 2000
#define F_  512
#define H_  512
#define HH_ 1024

// ---------------- device scratch (allowed: __device__ globals) ----------------
__device__ float g_wzh [B_ * TT_ * HH_];   // BN'd pre-activations: [b][t'][0:512]=wz, [512:1024]=wh  (128MB)
__device__ float g_hseq[B_ * TT_ * H_ ];   // all hidden states over the 2000-step scan (64MB)
__device__ float g_ln  [B_ * T_  * HH_];   // layernorm output (64MB)
__device__ float g_scale[HH_];
__device__ float g_bias [HH_];
__device__ unsigned int g_cnt[8];          // per-group monotonic step counters (fallback path)

// ---------------- packed fp32x2 FMA (double-rate FFMA on sm_103a) ----------------
__device__ __forceinline__ float2 ffma2(float2 a, float2 b, float2 c) {
    float2 d;
    asm("fma.rn.f32x2 %0, %1, %2, %3;"
        : "=l"(reinterpret_cast<unsigned long long &>(d))
        : "l"(reinterpret_cast<unsigned long long &>(a)),
          "l"(reinterpret_cast<unsigned long long &>(b)),
          "l"(reinterpret_cast<unsigned long long &>(c)));
    return d;
}

// ---------------- prep: fold BN into per-column scale/bias; reset counters ----------------
__global__ void prep_kernel(const float* __restrict__ bz, const float* __restrict__ bh,
                            const float* __restrict__ zg, const float* __restrict__ zb,
                            const float* __restrict__ zm, const float* __restrict__ zv,
                            const float* __restrict__ hg, const float* __restrict__ hb,
                            const float* __restrict__ hm, const float* __restrict__ hv) {
    int n = threadIdx.x;  // 1024 threads
    float sc, bi;
    if (n < 512) {
        sc = zg[n] * rsqrtf(zv[n] + 1e-5f);
        bi = (bz[n] - zm[n]) * sc + zb[n];
    } else {
        int j = n - 512;
        sc = hg[j] * rsqrtf(hv[j] + 1e-5f);
        bi = (bh[j] - hm[j]) * sc + hb[j];
    }
    g_scale[n] = sc;
    g_bias[n]  = bi;
    if (n < 8) g_cnt[n] = 0u;
}

// ---------------- phase 1: wzh = BN(x_cat @ [Wz;Wh]^T + b) ----------------
__global__ __launch_bounds__(256) void gemm_wzh(const float* __restrict__ x,
                                                const float* __restrict__ Wz,
                                                const float* __restrict__ Wh) {
    __shared__ __align__(16) float As[32][68];
    __shared__ __align__(16) float Bs[32][68];
    int tid = threadIdx.x;
    int tx = tid & 15, ty = tid >> 4;
    int m0 = blockIdx.y * 64, n0 = blockIdx.x * 64;

    float2 acc[4][2];
#pragma unroll
    for (int i = 0; i < 4; i++) { acc[i][0] = make_float2(0.f, 0.f); acc[i][1] = make_float2(0.f, 0.f); }

    for (int k0 = 0; k0 < 512; k0 += 32) {
#pragma unroll
        for (int u = 0; u < 2; u++) {
            int v  = tid * 2 + u;       // 0..511 float4 slots
            int mm = v >> 3;            // 0..63 row within tile
            int k4 = (v & 7) * 4;       // 0..28

            int m = m0 + mm;
            int b = m / TT_;
            int tp = m - b * TT_;
            const float* arow = (tp < T_) ? (x + ((size_t)(b * T_ + tp) << 9))
                                          : (x + ((size_t)((15 - b) * T_ + (tp - T_)) << 9));
            float4 av = *(const float4*)(arow + k0 + k4);
            As[k4 + 0][mm] = av.x; As[k4 + 1][mm] = av.y; As[k4 + 2][mm] = av.z; As[k4 + 3][mm] = av.w;

            int n = n0 + mm;
            const float* brow = (n < 512) ? (Wz + ((size_t)n << 9))
                                          : (Wh + ((size_t)(n - 512) << 9));
            float4 bv = *(const float4*)(brow + k0 + k4);
            Bs[k4 + 0][mm] = bv.x; Bs[k4 + 1][mm] = bv.y; Bs[k4 + 2][mm] = bv.z; Bs[k4 + 3][mm] = bv.w;
        }
        __syncthreads();
#pragma unroll
        for (int k = 0; k < 32; k++) {
            float4 a4 = *(const float4*)&As[k][ty * 4];
            float4 b4 = *(const float4*)&Bs[k][tx * 4];
            float2 b20 = make_float2(b4.x, b4.y), b21 = make_float2(b4.z, b4.w);
            float av[4] = {a4.x, a4.y, a4.z, a4.w};
#pragma unroll
            for (int i = 0; i < 4; i++) {
                float2 ad = make_float2(av[i], av[i]);
                acc[i][0] = ffma2(ad, b20, acc[i][0]);
                acc[i][1] = ffma2(ad, b21, acc[i][1]);
            }
        }
        __syncthreads();
    }
#pragma unroll
    for (int i = 0; i < 4; i++) {
        int m = m0 + ty * 4 + i;
        float* orow = g_wzh + (size_t)m * HH_ + n0 + tx * 4;
        int n = n0 + tx * 4;
        orow[0] = acc[i][0].x * g_scale[n + 0] + g_bias[n + 0];
        orow[1] = acc[i][0].y * g_scale[n + 1] + g_bias[n + 1];
        orow[2] = acc[i][1].x * g_scale[n + 2] + g_bias[n + 2];
        orow[3] = acc[i][1].y * g_scale[n + 3] + g_bias[n + 3];
    }
}

// ---------------- phase 2a: persistent scan, 16-CTA-cluster variant ----------------
// 8 clusters x 16 CTAs. Cluster g owns batches {2g, 2g+1}.
// CTA ci holds U rows [32ci,32ci+32) (z) and [512+32ci,+32) (h) in registers.
// Per-step handoff: stcg h -> L2, barrier.cluster (release/acquire), ldcg reload.
__global__ __launch_bounds__(512, 1) void scan_cluster(const float* __restrict__ U) {
    __shared__ float h_sm[2][512];
    __shared__ float red[2][8][64];

    int t   = threadIdx.x;
    int grp = blockIdx.x >> 4;   // cluster id 0..7
    int ci  = blockIdx.x & 15;   // rank within cluster
    int b0  = grp * 2;

    int r = t & 63;              // local row 0..63 (0..31 z, 32..63 h)
    int c = t >> 6;              // k-chunk 0..7 (64 k each)
    int urow = (r < 32) ? (ci * 32 + r) : (512 + ci * 32 + (r - 32));

    const float2* Up = (const float2*)(U + (size_t)urow * 512 + c * 64);
    float2 Ureg[32];
#pragma unroll
    for (int q = 0; q < 32; q++) Ureg[q] = __ldg(&Up[q]);

    for (int idx = t; idx < 1024; idx += 512) ((float*)h_sm)[idx] = 0.f;

    int bb = t >> 5, j = t & 31;           // only meaningful for t<64
    int bcur = b0 + bb;
    int cz = ci * 32 + j, ch = 512 + ci * 32 + j;
    float nz = 0.f, nh = 0.f;
    if (t < 64) {
        nz = __ldg(&g_wzh[(size_t)bcur * TT_ * HH_ + cz]);
        nh = __ldg(&g_wzh[(size_t)bcur * TT_ * HH_ + ch]);
    }
    __syncthreads();

    for (int s = 0; s < TT_; s++) {
        // matvec: this thread's 64-k chunk, both batches
        float2 a0 = make_float2(0.f, 0.f), a1 = make_float2(0.f, 0.f);
        const float2* h0 = (const float2*)&h_sm[0][c * 64];
        const float2* h1 = (const float2*)&h_sm[1][c * 64];
#pragma unroll
        for (int q = 0; q < 32; q++) {
            a0 = ffma2(Ureg[q], h0[q], a0);
            a1 = ffma2(Ureg[q], h1[q], a1);
        }
        red[0][c][r] = a0.x + a0.y;
        red[1][c][r] = a1.x + a1.y;
        __syncthreads();

        if (t < 64) {
            float uz = 0.f, uh = 0.f;
#pragma unroll
            for (int cc = 0; cc < 8; cc++) { uz += red[bb][cc][j]; uh += red[bb][cc][32 + j]; }
            float zt = __fdividef(1.f, 1.f + __expf(-(nz + uz)));
            float hc = fmaxf(nh + uh, 0.f);
            float hp = h_sm[bb][ci * 32 + j];
            float hn = zt * hp + (1.f - zt) * hc;
            __stcg(&g_hseq[((size_t)bcur * TT_ + s) * H_ + ci * 32 + j], hn);
            if (s + 1 < TT_) {
                nz = __ldg(&g_wzh[((size_t)bcur * TT_ + s + 1) * HH_ + cz]);
                nh = __ldg(&g_wzh[((size_t)bcur * TT_ + s + 1) * HH_ + ch]);
            }
        }
        // hardware cluster barrier: release (after stcg) + acquire (before ldcg)
        asm volatile("barrier.cluster.arrive.aligned;" ::: "memory");
        asm volatile("barrier.cluster.wait.aligned;"   ::: "memory");

        // reload full h (both batches) from L2: 512 threads x 1 float2
        {
            int b2 = t >> 8;          // 0..1
            int hh = (t & 255) << 1;  // 0..510 step 2
            const float2* src = (const float2*)&g_hseq[((size_t)(b0 + b2) * TT_ + s) * H_ + hh];
            float2 v = __ldcg(src);
            *(float2*)&h_sm[b2][hh] = v;
        }
        __syncthreads();
    }
}

// ---------------- phase 2b: fallback scan (L2 release/poll), proven correct ----------------
__global__ __launch_bounds__(512, 1) void scan_kernel(const float* __restrict__ U) {
    __shared__ float h_sm[2][512];
    __shared__ float red[2][8][64];

    int t   = threadIdx.x;
    int grp = blockIdx.x >> 4;
    int ci  = blockIdx.x & 15;
    int b0  = grp * 2;

    int r = t & 63;
    int c = t >> 6;
    int urow = (r < 32) ? (ci * 32 + r) : (512 + ci * 32 + (r - 32));

    const float2* Up = (const float2*)(U + (size_t)urow * 512 + c * 64);
    float2 Ureg[32];
#pragma unroll
    for (int q = 0; q < 32; q++) Ureg[q] = __ldg(&Up[q]);

    for (int idx = t; idx < 1024; idx += 512) ((float*)h_sm)[idx] = 0.f;

    int bb = t >> 5, j = t & 31;
    int bcur = b0 + bb;
    int cz = ci * 32 + j, ch = 512 + ci * 32 + j;
    float nz = 0.f, nh = 0.f;
    if (t < 64) {
        nz = __ldg(&g_wzh[(size_t)bcur * TT_ * HH_ + cz]);
        nh = __ldg(&g_wzh[(size_t)bcur * TT_ * HH_ + ch]);
    }
    __syncthreads();

    for (int s = 0; s < TT_; s++) {
        float2 a0 = make_float2(0.f, 0.f), a1 = make_float2(0.f, 0.f);
        const float2* h0 = (const float2*)&h_sm[0][c * 64];
        const float2* h1 = (const float2*)&h_sm[1][c * 64];
#pragma unroll
        for (int q = 0; q < 32; q++) {
            a0 = ffma2(Ureg[q], h0[q], a0);
            a1 = ffma2(Ureg[q], h1[q], a1);
        }
        red[0][c][r] = a0.x + a0.y;
        red[1][c][r] = a1.x + a1.y;
        __syncthreads();

        if (t < 64) {
            float uz = 0.f, uh = 0.f;
#pragma unroll
            for (int cc = 0; cc < 8; cc++) { uz += red[bb][cc][j]; uh += red[bb][cc][32 + j]; }
            float zt = __fdividef(1.f, 1.f + __expf(-(nz + uz)));
            float hc = fmaxf(nh + uh, 0.f);
            float hp = h_sm[bb][ci * 32 + j];
            float hn = zt * hp + (1.f - zt) * hc;
            g_hseq[((size_t)bcur * TT_ + s) * H_ + ci * 32 + j] = hn;
            if (s + 1 < TT_) {
                nz = __ldg(&g_wzh[((size_t)bcur * TT_ + s + 1) * HH_ + cz]);
                nh = __ldg(&g_wzh[((size_t)bcur * TT_ + s + 1) * HH_ + ch]);
            }
        }
        __threadfence();
        __syncthreads();
        if (t == 0) {
            atomicAdd(&g_cnt[grp], 1u);
            unsigned int target = (unsigned int)(16 * (s + 1));
            unsigned int v;
            do {
                asm volatile("ld.acquire.gpu.u32 %0, [%1];" : "=r"(v) : "l"(&g_cnt[grp]) : "memory");
            } while (v < target);
        }
        __syncthreads();
        for (int idx = t; idx < 1024; idx += 512) {
            int b2 = idx >> 9, hh = idx & 511;
            h_sm[b2][hh] = __ldcg(&g_hseq[((size_t)(b0 + b2) * TT_ + s) * H_ + hh]);
        }
        __syncthreads();
    }
}

// ---------------- phase 3: LayerNorm over concat(h_f, h_b) ----------------
__global__ __launch_bounds__(256) void ln_kernel(const float* __restrict__ lng,
                                                 const float* __restrict__ lnb) {
    __shared__ float s_sum[8], s_sq[8];
    int row = blockIdx.x;            // 0..15999
    int b = row / T_, tt = row - b * T_;
    int tid = threadIdx.x;
    int d = tid * 4;
    const float* base = (d < 512)
        ? (g_hseq + ((size_t)b * TT_ + tt) * H_ + d)
        : (g_hseq + ((size_t)(15 - b) * TT_ + T_ + tt) * H_ + (d - 512));
    float4 v = *(const float4*)base;
    float s = v.x + v.y + v.z + v.w;
    float q = v.x * v.x + v.y * v.y + v.z * v.z + v.w * v.w;
#pragma unroll
    for (int o = 16; o > 0; o >>= 1) {
        s += __shfl_down_sync(0xffffffffu, s, o);
        q += __shfl_down_sync(0xffffffffu, q, o);
    }
    int wid = tid >> 5, lid = tid & 31;
    if (lid == 0) { s_sum[wid] = s; s_sq[wid] = q; }
    __syncthreads();
    if (tid == 0) {
        float S = 0.f, Q = 0.f;
#pragma unroll
        for (int w = 0; w < 8; w++) { S += s_sum[w]; Q += s_sq[w]; }
        s_sum[0] = S; s_sq[0] = Q;
    }
    __syncthreads();
    float mu  = s_sum[0] * (1.f / 1024.f);
    float var = s_sq[0] * (1.f / 1024.f) - mu * mu;
    float inv = rsqrtf(var + 1e-5f);
    float4 g4 = *(const float4*)(lng + d);
    float4 b4 = *(const float4*)(lnb + d);
    float4 o;
    o.x = (v.x - mu) * inv * g4.x + b4.x;
    o.y = (v.y - mu) * inv * g4.y + b4.y;
    o.z = (v.z - mu) * inv * g4.z + b4.z;
    o.w = (v.w - mu) * inv * g4.w + b4.w;
    *(float4*)(g_ln + (size_t)row * HH_ + d) = o;
}

// ---------------- phase 4: out = tanh(ln_out @ pj_W^T + pj_b) ----------------
__global__ __launch_bounds__(256) void gemm_proj(const float* __restrict__ pjW,
                                                 const float* __restrict__ pjb,
                                                 float* __restrict__ out) {
    __shared__ __align__(16) float As[32][68];
    __shared__ __align__(16) float Bs[32][68];
    int tid = threadIdx.x;
    int tx = tid & 15, ty = tid >> 4;
    int m0 = blockIdx.y * 64, n0 = blockIdx.x * 64;

    float2 acc[4][2];
#pragma unroll
    for (int i = 0; i < 4; i++) { acc[i][0] = make_float2(0.f, 0.f); acc[i][1] = make_float2(0.f, 0.f); }

    for (int k0 = 0; k0 < 1024; k0 += 32) {
#pragma unroll
        for (int u = 0; u < 2; u++) {
            int v  = tid * 2 + u;
            int mm = v >> 3;
            int k4 = (v & 7) * 4;
            float4 av = *(const float4*)(g_ln + (size_t)(m0 + mm) * HH_ + k0 + k4);
            As[k4 + 0][mm] = av.x; As[k4 + 1][mm] = av.y; As[k4 + 2][mm] = av.z; As[k4 + 3][mm] = av.w;
            float4 bv = *(const float4*)(pjW + (size_t)(n0 + mm) * HH_ + k0 + k4);
            Bs[k4 + 0][mm] = bv.x; Bs[k4 + 1][mm] = bv.y; Bs[k4 + 2][mm] = bv.z; Bs[k4 + 3][mm] = bv.w;
        }
        __syncthreads();
#pragma unroll
        for (int k = 0; k < 32; k++) {
            float4 a4 = *(const float4*)&As[k][ty * 4];
            float4 b4 = *(const float4*)&Bs[k][tx * 4];
            float2 b20 = make_float2(b4.x, b4.y), b21 = make_float2(b4.z, b4.w);
            float av[4] = {a4.x, a4.y, a4.z, a4.w};
#pragma unroll
            for (int i = 0; i < 4; i++) {
                float2 ad = make_float2(av[i], av[i]);
                acc[i][0] = ffma2(ad, b20, acc[i][0]);
                acc[i][1] = ffma2(ad, b21, acc[i][1]);
            }
        }
        __syncthreads();
    }
#pragma unroll
    for (int i = 0; i < 4; i++) {
        int m = m0 + ty * 4 + i;
        int n = n0 + tx * 4;
        float* orow = out + (size_t)m * HH_ + n;
        orow[0] = tanhf(acc[i][0].x + pjb[n + 0]);
        orow[1] = tanhf(acc[i][0].y + pjb[n + 1]);
        orow[2] = tanhf(acc[i][1].x + pjb[n + 2]);
        orow[3] = tanhf(acc[i][1].y + pjb[n + 3]);
    }
}

// ---------------- tail: x_len pass-through ----------------
__global__ void tail_kernel(const int* __restrict__ xlen, float* __restrict__ out) {
    int t = threadIdx.x;
    if (t < B_) out[(size_t)B_ * T_ * HH_ + t] = (float)xlen[t];
}

extern "C" void kernel_launch(void* const* d_in, const int* in_sizes, int n_in,
                              void* d_out, int out_size) {
    const float* x   = (const float*)d_in[0];
    const int*   xl  = (const int*)  d_in[1];
    const float* Wz  = (const float*)d_in[2];
    const float* bz  = (const float*)d_in[3];
    const float* Wh  = (const float*)d_in[4];
    const float* bh  = (const float*)d_in[5];
    const float* U   = (const float*)d_in[6];
    const float* zg  = (const float*)d_in[7];
    const float* zb  = (const float*)d_in[8];
    const float* zm  = (const float*)d_in[9];
    const float* zv  = (const float*)d_in[10];
    const float* hg  = (const float*)d_in[11];
    const float* hb  = (const float*)d_in[12];
    const float* hm  = (const float*)d_in[13];
    const float* hv  = (const float*)d_in[14];
    const float* lng = (const float*)d_in[15];
    const float* lnb = (const float*)d_in[16];
    const float* pjW = (const float*)d_in[17];
    const float* pjb = (const float*)d_in[18];
    float* out = (float*)d_out;

    prep_kernel<<<1, 1024>>>(bz, bh, zg, zb, zm, zv, hg, hb, hm, hv);
    gemm_wzh<<<dim3(16, 500), 256>>>(x, Wz, Wh);

    // Try the 16-CTA-cluster scan; fall back to the L2-spin scan if unsupported.
    bool launched_cluster = false;
    {
        cudaFuncSetAttribute(scan_cluster, cudaFuncAttributeNonPortableClusterSizeAllowed, 1);
        (void)cudaGetLastError();

        cudaLaunchConfig_t cfg = {};
        cfg.gridDim  = dim3(128, 1, 1);
        cfg.blockDim = dim3(512, 1, 1);
        cfg.dynamicSmemBytes = 0;
        cfg.stream = 0;  // same (legacy default) stream as the <<<>>> launches
        cudaLaunchAttribute attrs[1];
        attrs[0].id = cudaLaunchAttributeClusterDimension;
        attrs[0].val.clusterDim.x = 16;
        attrs[0].val.clusterDim.y = 1;
        attrs[0].val.clusterDim.z = 1;
        cfg.attrs = attrs;
        cfg.numAttrs = 1;

        int maxClusters = 0;
        cudaError_t qe = cudaOccupancyMaxActiveClusters(&maxClusters, scan_cluster, &cfg);
        if (qe == cudaSuccess && maxClusters >= 8) {
            cudaError_t le = cudaLaunchKernelEx(&cfg, scan_cluster, U);
            if (le == cudaSuccess) launched_cluster = true;
            else (void)cudaGetLastError();
        } else {
            (void)cudaGetLastError();
        }
    }
    if (!launched_cluster) {
        scan_kernel<<<128, 512>>>(U);
    }

    ln_kernel<<<16000, 256>>>(lng, lnb);
    gemm_proj<<<dim3(16, 250), 256>>>(pjW, pjb, out);
    if (out_size >= B_ * T_ * HH_ + B_) {
        tail_kernel<<<1, 32>>>(xl, out);
    }
    (void)in_sizes; (void)n_in;
}